// round 4
// baseline (speedup 1.0000x reference)
#include <cuda_runtime.h>
#include <math.h>

#define BB   16
#define LL   1024
#define DM   64
#define HH   8
#define DKK  8
#define NROWS (BB*LL)

// ---------------- scratch (device globals: alloc-free) ----------------
__device__ float g_X[NROWS*DM];     // residual stream (b,l,d)
__device__ float g_Q[NROWS*DM];     // (b,h,l,k)
__device__ float g_K[NROWS*DM];
__device__ float g_V[NROWS*DM];
__device__ float g_C[NROWS*DM];     // attention concat output (b,l,h*DK+k)
__device__ float g_demo[BB*DM];
__device__ float g_mask[NROWS];
__device__ float g_awl[NROWS];

// ---------------- embedding: X = emb[varis] + CVE(values) + CVE(times) ----------------
__global__ void embed_kernel(const float* __restrict__ times, const float* __restrict__ values,
                             const int* __restrict__ varis, const float* __restrict__ emb,
                             const float* __restrict__ vW1, const float* __restrict__ vb1,
                             const float* __restrict__ vW2, const float* __restrict__ tW1,
                             const float* __restrict__ tb1, const float* __restrict__ tW2,
                             float* __restrict__ X, float* __restrict__ maskf)
{
    __shared__ float sv[4][8], st[4][8];
    int r = threadIdx.x >> 6, c = threadIdx.x & 63;
    int row = blockIdx.x * 4 + r;
    float vval = values[row];
    float tval = times[row];
    if (c < 8)       sv[r][c]   = tanhf(vval * vW1[c]   + vb1[c]);
    else if (c < 16) st[r][c-8] = tanhf(tval * tW1[c-8] + tb1[c-8]);
    __syncthreads();
    int vi = varis[row];
    float x = emb[vi*64 + c];
    #pragma unroll
    for (int u = 0; u < 8; u++) {
        x += sv[r][u] * vW2[u*64 + c];
        x += st[r][u] * tW2[u*64 + c];
    }
    X[row*64 + c] = x;
    if (c == 0) maskf[row] = (vi > 0) ? 1.0f : 0.0f;
}

// ---------------- demo encoder: tanh(tanh(demo@dW1)@dW2) ----------------
__global__ void demo_kernel(const float* __restrict__ demo, const float* __restrict__ dW1,
                            const float* __restrict__ db1, const float* __restrict__ dW2,
                            const float* __restrict__ db2, float* __restrict__ de)
{
    __shared__ float hh[128];
    int b = blockIdx.x, j = threadIdx.x;
    float a = db1[j];
    for (int i = 0; i < 50; i++) a += demo[b*50 + i] * dW1[i*128 + j];
    hh[j] = tanhf(a);
    __syncthreads();
    if (j < 64) {
        float e = db2[j];
        #pragma unroll
        for (int u = 0; u < 128; u++) e += hh[u] * dW2[u*64 + j];
        de[b*64 + j] = tanhf(e);
    }
}

// ---------------- fused QKV projection ----------------
// 192 threads, 16 rows/block. sW layout: [dd][col] col = 0..191 covering q|k|v cols.
__global__ void qkv_kernel(const float* __restrict__ X,
                           const float* __restrict__ Wq, const float* __restrict__ Wk,
                           const float* __restrict__ Wv,
                           float* __restrict__ Q, float* __restrict__ K, float* __restrict__ V)
{
    extern __shared__ float sm[];
    float* sW = sm;            // 12288 floats
    float* sX = sm + 12288;    // 1024 floats (16 rows x 64)
    const int tid = threadIdx.x;
    for (int idx = tid; idx < 12288; idx += 192) {
        int dd = idx / 192, col = idx % 192;
        int mat = col >> 6, c = col & 63;
        const float* W = (mat == 0) ? Wq : ((mat == 1) ? Wk : Wv);
        sW[idx] = W[((c >> 3) << 9) + (dd << 3) + (c & 7)];   // W[h][dd][k]
    }
    int rowbase = blockIdx.x * 16;
    for (int idx = tid; idx < 16*64; idx += 192) sX[idx] = X[rowbase*64 + idx];
    __syncthreads();

    int col4 = tid % 48;            // group of 4 contiguous cols
    int rr   = tid / 48;            // 0..3
    const float4* sW4 = (const float4*)sW;
    int col = col4 * 4;
    int mat = col >> 6, c = col & 63;
    float* OUT = (mat == 0) ? Q : ((mat == 1) ? K : V);
    int h = c >> 3, k = c & 7;
    for (int it = 0; it < 4; it++) {
        int rl = it*4 + rr;
        const float* xr = sX + rl*64;
        float4 acc = make_float4(0.f, 0.f, 0.f, 0.f);
        #pragma unroll
        for (int dd = 0; dd < 64; dd++) {
            float4 w = sW4[dd*48 + col4];
            float  x = xr[dd];
            acc.x += x*w.x; acc.y += x*w.y; acc.z += x*w.z; acc.w += x*w.w;
        }
        int row = rowbase + rl;
        int b = row >> 10, l = row & 1023;
        *((float4*)(OUT + ((((b<<3) + h) << 10) + l)*8 + k)) = acc;
    }
}

// ---------------- attention: per (b,h,query-block), K/V tile in smem, online softmax ----------------
__global__ void attn_kernel(const float* __restrict__ Q, const float* __restrict__ K,
                            const float* __restrict__ V, const float* __restrict__ maskf,
                            float* __restrict__ C)
{
    extern __shared__ float sm[];
    float* sK = sm;          // 8192
    float* sV = sm + 8192;   // 8192
    float* sM = sm + 16384;  // 1024
    int bh = blockIdx.x >> 2;
    int qb = blockIdx.x & 3;
    int b = bh >> 3, h = bh & 7;
    const float* Kp = K + bh * 8192;
    const float* Vp = V + bh * 8192;
    int tid = threadIdx.x;  // 256
    for (int i = tid; i < 8192; i += 256) { sK[i] = Kp[i]; sV[i] = Vp[i]; }
    for (int i = tid; i < 1024; i += 256) sM[i] = maskf[b*1024 + i];
    __syncthreads();

    int l = qb*256 + tid;
    float q[8];
    const float* qp = Q + (bh*1024 + l)*8;
    #pragma unroll
    for (int k = 0; k < 8; k++) q[k] = qp[k];

    float mmax = -3.0e38f, ssum = 0.f;
    float acc[8] = {0.f,0.f,0.f,0.f,0.f,0.f,0.f,0.f};
    const float4* sK4 = (const float4*)sK;
    const float4* sV4 = (const float4*)sV;
    for (int m = 0; m < 1024; m++) {
        float s;
        if (sM[m] != 0.f) {
            float4 k0 = sK4[m*2], k1 = sK4[m*2 + 1];
            s = q[0]*k0.x + q[1]*k0.y + q[2]*k0.z + q[3]*k0.w
              + q[4]*k1.x + q[5]*k1.y + q[6]*k1.z + q[7]*k1.w;
        } else {
            s = -1e-30f;   // reference uses MASK_ATTN = -1e-30 (NOT -inf)
        }
        if (s > mmax) {
            float corr = __expf(mmax - s);
            ssum *= corr;
            #pragma unroll
            for (int k = 0; k < 8; k++) acc[k] *= corr;
            mmax = s;
        }
        float p = __expf(s - mmax);
        ssum += p;
        float4 v0 = sV4[m*2], v1 = sV4[m*2 + 1];
        acc[0] += p*v0.x; acc[1] += p*v0.y; acc[2] += p*v0.z; acc[3] += p*v0.w;
        acc[4] += p*v1.x; acc[5] += p*v1.y; acc[6] += p*v1.z; acc[7] += p*v1.w;
    }
    float inv = 1.f / ssum;
    float* cp = C + (b*1024 + l)*64 + h*8;
    ((float4*)cp)[0] = make_float4(acc[0]*inv, acc[1]*inv, acc[2]*inv, acc[3]*inv);
    ((float4*)cp)[1] = make_float4(acc[4]*inv, acc[5]*inv, acc[6]*inv, acc[7]*inv);
}

// ---------------- out-projection + residual + LayerNorm (scalar gamma/beta) ----------------
__global__ void proj_ln_kernel(float* __restrict__ X, const float* __restrict__ C,
                               const float* __restrict__ Wo,
                               const float* __restrict__ gamma, const float* __restrict__ beta)
{
    __shared__ float sWo[4096];
    __shared__ float sC[256];
    __shared__ float red[256];
    __shared__ float sstat[8];
    int tid = threadIdx.x;  // 256
    for (int i = tid; i < 4096; i += 256) sWo[i] = Wo[i];  // [dd][c]
    int rowbase = blockIdx.x * 4;
    sC[tid] = C[rowbase*64 + tid];
    __syncthreads();

    int r = tid >> 6, c = tid & 63;
    int row = rowbase + r;
    float y = X[row*64 + c];
    const float* cr = sC + r*64;
    #pragma unroll
    for (int dd = 0; dd < 64; dd++) y += cr[dd] * sWo[dd*64 + c];
    red[tid] = y;
    __syncthreads();
    if (tid < 4) {
        float s = 0.f, s2 = 0.f;
        const float* rr = red + tid*64;
        #pragma unroll
        for (int i = 0; i < 64; i++) { float v = rr[i]; s += v; s2 += v*v; }
        float mean = s * (1.f/64.f);
        float var  = s2 * (1.f/64.f) - mean*mean;
        sstat[tid*2]   = mean;
        sstat[tid*2+1] = rsqrtf(var + 1e-14f);
    }
    __syncthreads();
    X[row*64 + c] = (y - sstat[r*2]) * sstat[r*2+1] * gamma[0] + beta[0];
}

// ---------------- FFN + residual + LayerNorm ----------------
__global__ void ffn_kernel(float* __restrict__ X,
                           const float* __restrict__ W1, const float* __restrict__ b1,
                           const float* __restrict__ W2, const float* __restrict__ b2,
                           const float* __restrict__ gamma, const float* __restrict__ beta)
{
    extern __shared__ float sm[];
    float* sW1   = sm;            // 8192  [dd][128]
    float* sW2   = sm + 8192;     // 8192  [j][64]
    float* sX    = sm + 16384;    // 512
    float* sH    = sm + 16896;    // 1024
    float* red   = sm + 17920;    // 512
    float* sstat = sm + 18432;    // 16
    int tid = threadIdx.x;  // 256
    for (int i = tid; i < 8192; i += 256) { sW1[i] = W1[i]; sW2[i] = W2[i]; }
    int rowbase = blockIdx.x * 8;
    for (int i = tid; i < 512; i += 256) sX[i] = X[rowbase*64 + i];
    __syncthreads();

    // stage 1: hidden = relu(X@W1 + b1)
    {
        int r = tid >> 5, jg = tid & 31;
        const float4* w4p = (const float4*)sW1;
        const float* xr = sX + r*64;
        float4 a = make_float4(b1[jg*4], b1[jg*4+1], b1[jg*4+2], b1[jg*4+3]);
        #pragma unroll
        for (int dd = 0; dd < 64; dd++) {
            float4 w = w4p[dd*32 + jg];
            float  x = xr[dd];
            a.x += x*w.x; a.y += x*w.y; a.z += x*w.z; a.w += x*w.w;
        }
        ((float4*)(sH + r*128))[jg] =
            make_float4(fmaxf(a.x,0.f), fmaxf(a.y,0.f), fmaxf(a.z,0.f), fmaxf(a.w,0.f));
    }
    __syncthreads();

    // stage 2: y = X + hidden@W2 + b2
    if (tid < 128) {
        int r = tid >> 4, cg = tid & 15;
        const float4* w4p = (const float4*)sW2;
        const float* hr = sH + r*128;
        int row = rowbase + r;
        float4 a   = *((const float4*)(X + row*64 + cg*4));
        float4 bb4 = *((const float4*)(b2 + cg*4));
        a.x += bb4.x; a.y += bb4.y; a.z += bb4.z; a.w += bb4.w;
        #pragma unroll
        for (int j = 0; j < 128; j++) {
            float4 w = w4p[j*16 + cg];
            float hv = hr[j];
            a.x += hv*w.x; a.y += hv*w.y; a.z += hv*w.z; a.w += hv*w.w;
        }
        ((float4*)(red + r*64))[cg] = a;
    }
    __syncthreads();
    if (tid < 8) {
        float s = 0.f, s2 = 0.f;
        const float* rr = red + tid*64;
        #pragma unroll
        for (int i = 0; i < 64; i++) { float v = rr[i]; s += v; s2 += v*v; }
        float mean = s * (1.f/64.f);
        sstat[tid*2]   = mean;
        sstat[tid*2+1] = rsqrtf(s2*(1.f/64.f) - mean*mean + 1e-14f);
    }
    __syncthreads();
    float g = gamma[0], bv = beta[0];
    #pragma unroll
    for (int p = 0; p < 2; p++) {
        int idx = tid + p*256;
        int r = idx >> 6;
        X[(rowbase + r)*64 + (idx & 63)] = (red[idx] - sstat[r*2]) * sstat[r*2+1] * g + bv;
    }
}

// ---------------- attention-pool logits: tanh(X@aW1+ab1)@aW2 ----------------
__global__ void aw_kernel(const float* __restrict__ X, const float* __restrict__ aW1,
                          const float* __restrict__ ab1, const float* __restrict__ aW2,
                          float* __restrict__ awl)
{
    __shared__ float red[128];
    int row = blockIdx.x;
    int j = threadIdx.x;  // 128
    const float* xr = X + row*64;
    float a = ab1[j];
    #pragma unroll
    for (int dd = 0; dd < 64; dd++) a += xr[dd] * aW1[dd*128 + j];
    red[j] = tanhf(a) * aW2[j];
    __syncthreads();
    for (int st = 64; st > 0; st >>= 1) {
        if (j < st) red[j] += red[j + st];
        __syncthreads();
    }
    if (j == 0) awl[row] = red[0];
}

// ---------------- masked softmax pool + head ----------------
__global__ void pool_kernel(const float* __restrict__ X, const float* __restrict__ awl,
                            const float* __restrict__ maskf, const float* __restrict__ demoe,
                            const float* __restrict__ Wout, const float* __restrict__ bout,
                            float* __restrict__ out)
{
    __shared__ float sw[1024];
    __shared__ float red[256];
    __shared__ float conc[128];
    int b = blockIdx.x, tid = threadIdx.x;  // 256
    for (int l = tid; l < 1024; l += 256)
        sw[l] = (maskf[b*1024 + l] != 0.f) ? awl[b*1024 + l] : -1e30f;
    __syncthreads();
    float mx = -3.0e38f;
    for (int l = tid; l < 1024; l += 256) mx = fmaxf(mx, sw[l]);
    red[tid] = mx; __syncthreads();
    for (int st = 128; st > 0; st >>= 1) {
        if (tid < st) red[tid] = fmaxf(red[tid], red[tid + st]);
        __syncthreads();
    }
    mx = red[0];
    __syncthreads();
    float se = 0.f;
    for (int l = tid; l < 1024; l += 256) { float e = __expf(sw[l] - mx); sw[l] = e; se += e; }
    red[tid] = se; __syncthreads();
    for (int st = 128; st > 0; st >>= 1) {
        if (tid < st) red[tid] += red[tid + st];
        __syncthreads();
    }
    float inv = 1.f / red[0];
    __syncthreads();
    if (tid < 64) {
        float f = 0.f;
        const float* xb = X + b*1024*64;
        for (int l = 0; l < 1024; l++) f += sw[l] * xb[l*64 + tid];
        conc[tid] = f * inv;
    } else if (tid < 128) {
        conc[tid] = demoe[b*64 + (tid - 64)];
    }
    __syncthreads();
    if (tid < 128) red[tid] = conc[tid] * Wout[tid]; else red[tid] = 0.f;
    __syncthreads();
    for (int st = 128; st > 0; st >>= 1) {
        if (tid < st) red[tid] += red[tid + st];
        __syncthreads();
    }
    if (tid == 0) out[b] = 1.f / (1.f + __expf(-(red[0] + bout[0])));
}

// ---------------- launcher ----------------
extern "C" void kernel_launch(void* const* d_in, const int* in_sizes, int n_in,
                              void* d_out, int out_size)
{
    const float* demo  = (const float*)d_in[0];
    const float* times = (const float*)d_in[1];
    const float* values= (const float*)d_in[2];
    const int*   varis = (const int*)  d_in[3];
    const float* emb   = (const float*)d_in[4];
    const float* vW1   = (const float*)d_in[5];
    const float* vb1   = (const float*)d_in[6];
    const float* vW2   = (const float*)d_in[7];
    const float* tW1   = (const float*)d_in[8];
    const float* tb1   = (const float*)d_in[9];
    const float* tW2   = (const float*)d_in[10];
    const float* Wq    = (const float*)d_in[11];
    const float* Wk    = (const float*)d_in[12];
    const float* Wv    = (const float*)d_in[13];
    const float* Wo    = (const float*)d_in[14];
    const float* W1    = (const float*)d_in[15];
    const float* b1    = (const float*)d_in[16];
    const float* W2    = (const float*)d_in[17];
    const float* b2    = (const float*)d_in[18];
    const float* gamma = (const float*)d_in[19];
    const float* beta  = (const float*)d_in[20];
    const float* aW1   = (const float*)d_in[21];
    const float* ab1   = (const float*)d_in[22];
    const float* aW2   = (const float*)d_in[23];
    const float* dW1   = (const float*)d_in[24];
    const float* db1   = (const float*)d_in[25];
    const float* dW2   = (const float*)d_in[26];
    const float* db2   = (const float*)d_in[27];
    const float* Wout  = (const float*)d_in[28];
    const float* bout  = (const float*)d_in[29];
    float* out = (float*)d_out;

    float *X, *Qb, *Kb, *Vb, *Cb, *de, *mk, *awl;
    cudaGetSymbolAddress((void**)&X,   g_X);
    cudaGetSymbolAddress((void**)&Qb,  g_Q);
    cudaGetSymbolAddress((void**)&Kb,  g_K);
    cudaGetSymbolAddress((void**)&Vb,  g_V);
    cudaGetSymbolAddress((void**)&Cb,  g_C);
    cudaGetSymbolAddress((void**)&de,  g_demo);
    cudaGetSymbolAddress((void**)&mk,  g_mask);
    cudaGetSymbolAddress((void**)&awl, g_awl);

    cudaFuncSetAttribute(qkv_kernel,  cudaFuncAttributeMaxDynamicSharedMemorySize, 53248);
    cudaFuncSetAttribute(attn_kernel, cudaFuncAttributeMaxDynamicSharedMemorySize, 69632);
    cudaFuncSetAttribute(ffn_kernel,  cudaFuncAttributeMaxDynamicSharedMemorySize, 73792);

    embed_kernel<<<4096, 256>>>(times, values, varis, emb, vW1, vb1, vW2, tW1, tb1, tW2, X, mk);
    demo_kernel<<<16, 128>>>(demo, dW1, db1, dW2, db2, de);

    for (int i = 0; i < 2; i++) {
        qkv_kernel<<<1024, 192, 53248>>>(X, Wq + i*4096, Wk + i*4096, Wv + i*4096, Qb, Kb, Vb);
        attn_kernel<<<512, 256, 69632>>>(Qb, Kb, Vb, mk, Cb);
        proj_ln_kernel<<<4096, 256>>>(X, Cb, Wo + i*4096, gamma + 2*i, beta + 2*i);
        ffn_kernel<<<2048, 256, 73792>>>(X, W1 + i*8192, b1 + i*128, W2 + i*8192, b2 + i*64,
                                         gamma + 2*i + 1, beta + 2*i + 1);
    }

    aw_kernel<<<16384, 128>>>(X, aW1, ab1, aW2, awl);
    pool_kernel<<<16, 256>>>(X, awl, mk, de, Wout, bout, out);
}

// round 8
// speedup vs baseline: 1.4635x; 1.4635x over previous
#include <cuda_runtime.h>
#include <math.h>

#define BB   16
#define LL   1024
#define DM   64
#define HH   8
#define DKK  8
#define NROWS (BB*LL)

// ---------------- scratch (device globals: alloc-free) ----------------
__device__ float g_X[NROWS*DM];     // residual stream (b,l,d)
__device__ float g_Q[NROWS*DM];     // (b,h,l,k)
__device__ float g_K[NROWS*DM];
__device__ float g_V[NROWS*DM];
__device__ float g_C[NROWS*DM];     // attention concat output (b,l,h*DK+k)
__device__ float g_demo[BB*DM];
__device__ float g_mask[NROWS];
__device__ float g_awl[NROWS];

// ---------------- embedding: X = emb[varis] + CVE(values) + CVE(times) ----------------
__global__ void embed_kernel(const float* __restrict__ times, const float* __restrict__ values,
                             const int* __restrict__ varis, const float* __restrict__ emb,
                             const float* __restrict__ vW1, const float* __restrict__ vb1,
                             const float* __restrict__ vW2, const float* __restrict__ tW1,
                             const float* __restrict__ tb1, const float* __restrict__ tW2,
                             float* __restrict__ X, float* __restrict__ maskf)
{
    __shared__ float sv[4][8], st[4][8];
    int r = threadIdx.x >> 6, c = threadIdx.x & 63;
    int row = blockIdx.x * 4 + r;
    float vval = values[row];
    float tval = times[row];
    if (c < 8)       sv[r][c]   = tanhf(vval * vW1[c]   + vb1[c]);
    else if (c < 16) st[r][c-8] = tanhf(tval * tW1[c-8] + tb1[c-8]);
    __syncthreads();
    int vi = varis[row];
    float x = emb[vi*64 + c];
    #pragma unroll
    for (int u = 0; u < 8; u++) {
        x += sv[r][u] * vW2[u*64 + c];
        x += st[r][u] * tW2[u*64 + c];
    }
    X[row*64 + c] = x;
    if (c == 0) maskf[row] = (vi > 0) ? 1.0f : 0.0f;
}

// ---------------- demo encoder: tanh(tanh(demo@dW1)@dW2) ----------------
__global__ void demo_kernel(const float* __restrict__ demo, const float* __restrict__ dW1,
                            const float* __restrict__ db1, const float* __restrict__ dW2,
                            const float* __restrict__ db2, float* __restrict__ de)
{
    __shared__ float hh[128];
    int b = blockIdx.x, j = threadIdx.x;
    float a = db1[j];
    for (int i = 0; i < 50; i++) a += demo[b*50 + i] * dW1[i*128 + j];
    hh[j] = tanhf(a);
    __syncthreads();
    if (j < 64) {
        float e = db2[j];
        #pragma unroll
        for (int u = 0; u < 128; u++) e += hh[u] * dW2[u*64 + j];
        de[b*64 + j] = tanhf(e);
    }
}

// ---------------- fused QKV projection ----------------
__global__ void qkv_kernel(const float* __restrict__ X,
                           const float* __restrict__ Wq, const float* __restrict__ Wk,
                           const float* __restrict__ Wv,
                           float* __restrict__ Q, float* __restrict__ K, float* __restrict__ V)
{
    extern __shared__ float sm[];
    float* sW = sm;            // 12288 floats
    float* sX = sm + 12288;    // 1024 floats (16 rows x 64)
    const int tid = threadIdx.x;
    for (int idx = tid; idx < 12288; idx += 192) {
        int dd = idx / 192, col = idx % 192;
        int mat = col >> 6, c = col & 63;
        const float* W = (mat == 0) ? Wq : ((mat == 1) ? Wk : Wv);
        sW[idx] = W[((c >> 3) << 9) + (dd << 3) + (c & 7)];   // W[h][dd][k]
    }
    int rowbase = blockIdx.x * 16;
    for (int idx = tid; idx < 16*64; idx += 192) sX[idx] = X[rowbase*64 + idx];
    __syncthreads();

    int col4 = tid % 48;            // group of 4 contiguous cols
    int rr   = tid / 48;            // 0..3
    const float4* sW4 = (const float4*)sW;
    int col = col4 * 4;
    int mat = col >> 6, c = col & 63;
    float* OUT = (mat == 0) ? Q : ((mat == 1) ? K : V);
    int h = c >> 3, k = c & 7;
    for (int it = 0; it < 4; it++) {
        int rl = it*4 + rr;
        const float* xr = sX + rl*64;
        float4 acc = make_float4(0.f, 0.f, 0.f, 0.f);
        #pragma unroll
        for (int dd = 0; dd < 64; dd++) {
            float4 w = sW4[dd*48 + col4];
            float  x = xr[dd];
            acc.x += x*w.x; acc.y += x*w.y; acc.z += x*w.z; acc.w += x*w.w;
        }
        int row = rowbase + rl;
        int b = row >> 10, l = row & 1023;
        *((float4*)(OUT + ((((b<<3) + h) << 10) + l)*8 + k)) = acc;
    }
}

// ---------------- attention v2 ----------------
// Mask folded into K (masked rows zeroed -> score 0 -> exp=1, bit-identical to
// exp(-1e-30)). No online max: softmax is shift-invariant, scores are O(10).
// 2 queries/thread, 256 blocks (bh*2 + half), 256 threads.
__global__ void __launch_bounds__(256, 3)
attn_kernel(const float* __restrict__ Q, const float* __restrict__ K,
            const float* __restrict__ V, const float* __restrict__ maskf,
            float* __restrict__ C)
{
    extern __shared__ float sm[];
    float* sK = sm;          // 8192
    float* sV = sm + 8192;   // 8192
    int bh = blockIdx.x >> 1;
    int qh = blockIdx.x & 1;
    int b = bh >> 3, h = bh & 7;
    const float* Kp = K + bh * 8192;
    const float* Vp = V + bh * 8192;
    const float* mp = maskf + b * 1024;
    int tid = threadIdx.x;  // 256
    for (int i = tid; i < 8192; i += 256) {
        sV[i] = Vp[i];
        sK[i] = Kp[i] * mp[i >> 3];   // zero masked K rows
    }
    __syncthreads();

    int l0 = qh*512 + tid;
    int l1 = l0 + 256;
    float q0[8], q1[8];
    const float* qp0 = Q + (bh*1024 + l0)*8;
    const float* qp1 = Q + (bh*1024 + l1)*8;
    #pragma unroll
    for (int k = 0; k < 8; k++) { q0[k] = qp0[k]; q1[k] = qp1[k]; }

    float ssum0 = 0.f, ssum1 = 0.f;
    float acc0[8] = {0,0,0,0,0,0,0,0};
    float acc1[8] = {0,0,0,0,0,0,0,0};
    const float4* sK4 = (const float4*)sK;
    const float4* sV4 = (const float4*)sV;
    #pragma unroll 2
    for (int m = 0; m < 1024; m++) {
        float4 k0 = sK4[m*2], k1 = sK4[m*2 + 1];
        float s0 = q0[0]*k0.x + q0[1]*k0.y + q0[2]*k0.z + q0[3]*k0.w
                 + q0[4]*k1.x + q0[5]*k1.y + q0[6]*k1.z + q0[7]*k1.w;
        float s1 = q1[0]*k0.x + q1[1]*k0.y + q1[2]*k0.z + q1[3]*k0.w
                 + q1[4]*k1.x + q1[5]*k1.y + q1[6]*k1.z + q1[7]*k1.w;
        float p0 = __expf(s0);
        float p1 = __expf(s1);
        ssum0 += p0; ssum1 += p1;
        float4 v0 = sV4[m*2], v1 = sV4[m*2 + 1];
        acc0[0] += p0*v0.x; acc0[1] += p0*v0.y; acc0[2] += p0*v0.z; acc0[3] += p0*v0.w;
        acc0[4] += p0*v1.x; acc0[5] += p0*v1.y; acc0[6] += p0*v1.z; acc0[7] += p0*v1.w;
        acc1[0] += p1*v0.x; acc1[1] += p1*v0.y; acc1[2] += p1*v0.z; acc1[3] += p1*v0.w;
        acc1[4] += p1*v1.x; acc1[5] += p1*v1.y; acc1[6] += p1*v1.z; acc1[7] += p1*v1.w;
    }
    float inv0 = 1.f / ssum0;
    float inv1 = 1.f / ssum1;
    float* cp0 = C + (b*1024 + l0)*64 + h*8;
    float* cp1 = C + (b*1024 + l1)*64 + h*8;
    ((float4*)cp0)[0] = make_float4(acc0[0]*inv0, acc0[1]*inv0, acc0[2]*inv0, acc0[3]*inv0);
    ((float4*)cp0)[1] = make_float4(acc0[4]*inv0, acc0[5]*inv0, acc0[6]*inv0, acc0[7]*inv0);
    ((float4*)cp1)[0] = make_float4(acc1[0]*inv1, acc1[1]*inv1, acc1[2]*inv1, acc1[3]*inv1);
    ((float4*)cp1)[1] = make_float4(acc1[4]*inv1, acc1[5]*inv1, acc1[6]*inv1, acc1[7]*inv1);
}

// ---------------- out-projection + residual + LayerNorm v2 (warp-per-row) ----------------
__global__ void proj_ln_kernel(float* __restrict__ X, const float* __restrict__ C,
                               const float* __restrict__ Wo,
                               const float* __restrict__ gamma, const float* __restrict__ beta)
{
    __shared__ float sWo[4096];
    __shared__ float sC[512];
    int tid = threadIdx.x;  // 256 = 8 warps = 8 rows
    for (int i = tid; i < 4096; i += 256) sWo[i] = Wo[i];  // [dd][c]
    int rowbase = blockIdx.x * 8;
    for (int i = tid; i < 512; i += 256) sC[i] = C[rowbase*64 + i];
    __syncthreads();

    int w = tid >> 5, lane = tid & 31;
    int row = rowbase + w;
    int c0 = lane, c1 = lane + 32;
    float y0 = X[row*64 + c0];
    float y1 = X[row*64 + c1];
    const float* cr = sC + w*64;
    #pragma unroll
    for (int dd = 0; dd < 64; dd++) {
        float cv = cr[dd];
        y0 += cv * sWo[dd*64 + c0];
        y1 += cv * sWo[dd*64 + c1];
    }
    float s  = y0 + y1;
    float s2 = y0*y0 + y1*y1;
    #pragma unroll
    for (int o = 16; o > 0; o >>= 1) {
        s  += __shfl_xor_sync(0xffffffffu, s,  o);
        s2 += __shfl_xor_sync(0xffffffffu, s2, o);
    }
    float mean = s * (1.f/64.f);
    float rstd = rsqrtf(s2*(1.f/64.f) - mean*mean + 1e-14f);
    float g = gamma[0], bt = beta[0];
    X[row*64 + c0] = (y0 - mean) * rstd * g + bt;
    X[row*64 + c1] = (y1 - mean) * rstd * g + bt;
}

// ---------------- FFN + residual + LayerNorm ----------------
__global__ void ffn_kernel(float* __restrict__ X,
                           const float* __restrict__ W1, const float* __restrict__ b1,
                           const float* __restrict__ W2, const float* __restrict__ b2,
                           const float* __restrict__ gamma, const float* __restrict__ beta)
{
    extern __shared__ float sm[];
    float* sW1   = sm;            // 8192  [dd][128]
    float* sW2   = sm + 8192;     // 8192  [j][64]
    float* sX    = sm + 16384;    // 512
    float* sH    = sm + 16896;    // 1024
    float* red   = sm + 17920;    // 512
    float* sstat = sm + 18432;    // 16
    int tid = threadIdx.x;  // 256
    for (int i = tid; i < 8192; i += 256) { sW1[i] = W1[i]; sW2[i] = W2[i]; }
    int rowbase = blockIdx.x * 8;
    for (int i = tid; i < 512; i += 256) sX[i] = X[rowbase*64 + i];
    __syncthreads();

    // stage 1: hidden = relu(X@W1 + b1)
    {
        int r = tid >> 5, jg = tid & 31;
        const float4* w4p = (const float4*)sW1;
        const float* xr = sX + r*64;
        float4 a = make_float4(b1[jg*4], b1[jg*4+1], b1[jg*4+2], b1[jg*4+3]);
        #pragma unroll
        for (int dd = 0; dd < 64; dd++) {
            float4 w = w4p[dd*32 + jg];
            float  x = xr[dd];
            a.x += x*w.x; a.y += x*w.y; a.z += x*w.z; a.w += x*w.w;
        }
        ((float4*)(sH + r*128))[jg] =
            make_float4(fmaxf(a.x,0.f), fmaxf(a.y,0.f), fmaxf(a.z,0.f), fmaxf(a.w,0.f));
    }
    __syncthreads();

    // stage 2: y = X + hidden@W2 + b2
    if (tid < 128) {
        int r = tid >> 4, cg = tid & 15;
        const float4* w4p = (const float4*)sW2;
        const float* hr = sH + r*128;
        int row = rowbase + r;
        float4 a   = *((const float4*)(X + row*64 + cg*4));
        float4 bb4 = *((const float4*)(b2 + cg*4));
        a.x += bb4.x; a.y += bb4.y; a.z += bb4.z; a.w += bb4.w;
        #pragma unroll
        for (int j = 0; j < 128; j++) {
            float4 w = w4p[j*16 + cg];
            float hv = hr[j];
            a.x += hv*w.x; a.y += hv*w.y; a.z += hv*w.z; a.w += hv*w.w;
        }
        ((float4*)(red + r*64))[cg] = a;
    }
    __syncthreads();
    if (tid < 8) {
        float s = 0.f, s2 = 0.f;
        const float* rr = red + tid*64;
        #pragma unroll
        for (int i = 0; i < 64; i++) { float v = rr[i]; s += v; s2 += v*v; }
        float mean = s * (1.f/64.f);
        sstat[tid*2]   = mean;
        sstat[tid*2+1] = rsqrtf(s2*(1.f/64.f) - mean*mean + 1e-14f);
    }
    __syncthreads();
    float g = gamma[0], bv = beta[0];
    #pragma unroll
    for (int p = 0; p < 2; p++) {
        int idx = tid + p*256;
        int r = idx >> 6;
        X[(rowbase + r)*64 + (idx & 63)] = (red[idx] - sstat[r*2]) * sstat[r*2+1] * g + bv;
    }
}

// ---------------- attention-pool logits v2: 8 rows/block, aW1 in smem ----------------
__global__ void aw_kernel(const float* __restrict__ X, const float* __restrict__ aW1,
                          const float* __restrict__ ab1, const float* __restrict__ aW2,
                          float* __restrict__ awl)
{
    __shared__ float sW[8192];     // aW1 [64][128]
    __shared__ float sB[128];      // ab1
    __shared__ float sA2[128];     // aW2
    __shared__ float sXr[512];     // 8 rows x 64
    int tid = threadIdx.x;  // 256
    for (int i = tid; i < 8192; i += 256) sW[i] = aW1[i];
    if (tid < 128) { sB[tid] = ab1[tid]; sA2[tid] = aW2[tid]; }
    int rowbase = blockIdx.x * 8;
    for (int i = tid; i < 512; i += 256) sXr[i] = X[rowbase*64 + i];
    __syncthreads();

    int w = tid >> 5, lane = tid & 31;
    const float* xr = sXr + w*64;
    int j4 = lane * 4;
    float4 a = make_float4(sB[j4], sB[j4+1], sB[j4+2], sB[j4+3]);
    const float4* w4p = (const float4*)sW;
    #pragma unroll
    for (int dd = 0; dd < 64; dd++) {
        float4 wv = w4p[dd*32 + lane];
        float  x  = xr[dd];
        a.x += x*wv.x; a.y += x*wv.y; a.z += x*wv.z; a.w += x*wv.w;
    }
    float val = tanhf(a.x)*sA2[j4] + tanhf(a.y)*sA2[j4+1]
              + tanhf(a.z)*sA2[j4+2] + tanhf(a.w)*sA2[j4+3];
    #pragma unroll
    for (int o = 16; o > 0; o >>= 1) val += __shfl_xor_sync(0xffffffffu, val, o);
    if (lane == 0) awl[rowbase + w] = val;
}

// ---------------- masked softmax pool + head ----------------
__global__ void pool_kernel(const float* __restrict__ X, const float* __restrict__ awl,
                            const float* __restrict__ maskf, const float* __restrict__ demoe,
                            const float* __restrict__ Wout, const float* __restrict__ bout,
                            float* __restrict__ out)
{
    __shared__ float sw[1024];
    __shared__ float red[256];
    __shared__ float part[4][64];
    __shared__ float conc[128];
    int b = blockIdx.x, tid = threadIdx.x;  // 256
    for (int l = tid; l < 1024; l += 256)
        sw[l] = (maskf[b*1024 + l] != 0.f) ? awl[b*1024 + l] : -1e30f;
    __syncthreads();
    float mx = -3.0e38f;
    for (int l = tid; l < 1024; l += 256) mx = fmaxf(mx, sw[l]);
    red[tid] = mx; __syncthreads();
    for (int st = 128; st > 0; st >>= 1) {
        if (tid < st) red[tid] = fmaxf(red[tid], red[tid + st]);
        __syncthreads();
    }
    mx = red[0];
    __syncthreads();
    float se = 0.f;
    for (int l = tid; l < 1024; l += 256) { float e = __expf(sw[l] - mx); sw[l] = e; se += e; }
    red[tid] = se; __syncthreads();
    for (int st = 128; st > 0; st >>= 1) {
        if (tid < st) red[tid] += red[tid + st];
        __syncthreads();
    }
    float inv = 1.f / red[0];
    __syncthreads();
    // fused = sum_l sw[l]*X[l,:] — all 256 threads (64 cols x 4 chunks)
    {
        int col = tid & 63, ch = tid >> 6;
        const float* xb = X + b*1024*64;
        float f = 0.f;
        for (int i = 0; i < 256; i++) {
            int l = ch*256 + i;
            f += sw[l] * xb[l*64 + col];
        }
        part[ch][col] = f;
    }
    __syncthreads();
    if (tid < 64) {
        conc[tid] = (part[0][tid] + part[1][tid] + part[2][tid] + part[3][tid]) * inv;
    } else if (tid < 128) {
        conc[tid] = demoe[b*64 + (tid - 64)];
    }
    __syncthreads();
    if (tid < 128) red[tid] = conc[tid] * Wout[tid]; else red[tid] = 0.f;
    __syncthreads();
    for (int st = 128; st > 0; st >>= 1) {
        if (tid < st) red[tid] += red[tid + st];
        __syncthreads();
    }
    if (tid == 0) out[b] = 1.f / (1.f + __expf(-(red[0] + bout[0])));
}

// ---------------- launcher ----------------
extern "C" void kernel_launch(void* const* d_in, const int* in_sizes, int n_in,
                              void* d_out, int out_size)
{
    const float* demo  = (const float*)d_in[0];
    const float* times = (const float*)d_in[1];
    const float* values= (const float*)d_in[2];
    const int*   varis = (const int*)  d_in[3];
    const float* emb   = (const float*)d_in[4];
    const float* vW1   = (const float*)d_in[5];
    const float* vb1   = (const float*)d_in[6];
    const float* vW2   = (const float*)d_in[7];
    const float* tW1   = (const float*)d_in[8];
    const float* tb1   = (const float*)d_in[9];
    const float* tW2   = (const float*)d_in[10];
    const float* Wq    = (const float*)d_in[11];
    const float* Wk    = (const float*)d_in[12];
    const float* Wv    = (const float*)d_in[13];
    const float* Wo    = (const float*)d_in[14];
    const float* W1    = (const float*)d_in[15];
    const float* b1    = (const float*)d_in[16];
    const float* W2    = (const float*)d_in[17];
    const float* b2    = (const float*)d_in[18];
    const float* gamma = (const float*)d_in[19];
    const float* beta  = (const float*)d_in[20];
    const float* aW1   = (const float*)d_in[21];
    const float* ab1   = (const float*)d_in[22];
    const float* aW2   = (const float*)d_in[23];
    const float* dW1   = (const float*)d_in[24];
    const float* db1   = (const float*)d_in[25];
    const float* dW2   = (const float*)d_in[26];
    const float* db2   = (const float*)d_in[27];
    const float* Wout  = (const float*)d_in[28];
    const float* bout  = (const float*)d_in[29];
    float* out = (float*)d_out;

    float *X, *Qb, *Kb, *Vb, *Cb, *de, *mk, *awl;
    cudaGetSymbolAddress((void**)&X,   g_X);
    cudaGetSymbolAddress((void**)&Qb,  g_Q);
    cudaGetSymbolAddress((void**)&Kb,  g_K);
    cudaGetSymbolAddress((void**)&Vb,  g_V);
    cudaGetSymbolAddress((void**)&Cb,  g_C);
    cudaGetSymbolAddress((void**)&de,  g_demo);
    cudaGetSymbolAddress((void**)&mk,  g_mask);
    cudaGetSymbolAddress((void**)&awl, g_awl);

    cudaFuncSetAttribute(qkv_kernel,  cudaFuncAttributeMaxDynamicSharedMemorySize, 53248);
    cudaFuncSetAttribute(attn_kernel, cudaFuncAttributeMaxDynamicSharedMemorySize, 65536);
    cudaFuncSetAttribute(ffn_kernel,  cudaFuncAttributeMaxDynamicSharedMemorySize, 73792);

    embed_kernel<<<4096, 256>>>(times, values, varis, emb, vW1, vb1, vW2, tW1, tb1, tW2, X, mk);
    demo_kernel<<<16, 128>>>(demo, dW1, db1, dW2, db2, de);

    for (int i = 0; i < 2; i++) {
        qkv_kernel<<<1024, 192, 53248>>>(X, Wq + i*4096, Wk + i*4096, Wv + i*4096, Qb, Kb, Vb);
        attn_kernel<<<256, 256, 65536>>>(Qb, Kb, Vb, mk, Cb);
        proj_ln_kernel<<<2048, 256>>>(X, Cb, Wo + i*4096, gamma + 2*i, beta + 2*i);
        ffn_kernel<<<2048, 256, 73792>>>(X, W1 + i*8192, b1 + i*128, W2 + i*8192, b2 + i*64,
                                         gamma + 2*i + 1, beta + 2*i + 1);
    }

    aw_kernel<<<2048, 256>>>(X, aW1, ab1, aW2, awl);
    pool_kernel<<<16, 256>>>(X, awl, mk, de, Wout, bout, out);
}

// round 11
// speedup vs baseline: 1.4866x; 1.0158x over previous
#include <cuda_runtime.h>
#include <math.h>

#define BB   16
#define LL   1024
#define DM   64
#define HH   8
#define DKK  8
#define NROWS (BB*LL)

// ---------------- scratch (device globals: alloc-free) ----------------
__device__ float g_X[NROWS*DM];     // residual stream (b,l,d)
__device__ float g_Q[NROWS*DM];     // (b,h,l,k)
__device__ float g_K[NROWS*DM];
__device__ float g_V[NROWS*DM];
__device__ float g_C[NROWS*DM];     // attention concat output (b,l,h*DK+k)
__device__ float g_demo[BB*DM];
__device__ float g_mask[NROWS];
__device__ float g_awl[NROWS];

// ---- packed f32x2 helpers (FFMA2: PTX-only on sm_103a) ----
__device__ __forceinline__ unsigned long long pk2(float lo, float hi) {
    unsigned long long r;
    asm("mov.b64 %0, {%1, %2};" : "=l"(r) : "f"(lo), "f"(hi));
    return r;
}
__device__ __forceinline__ void upk2(unsigned long long v, float& lo, float& hi) {
    asm("mov.b64 {%0, %1}, %2;" : "=f"(lo), "=f"(hi) : "l"(v));
}
__device__ __forceinline__ unsigned long long fma2(unsigned long long a,
                                                   unsigned long long b,
                                                   unsigned long long c) {
    unsigned long long d;
    asm("fma.rn.f32x2 %0, %1, %2, %3;" : "=l"(d) : "l"(a), "l"(b), "l"(c));
    return d;
}
__device__ __forceinline__ float ex2f(float x) {
    float r;
    asm("ex2.approx.f32 %0, %1;" : "=f"(r) : "f"(x));
    return r;
}

// ---------------- embedding: X = emb[varis] + CVE(values) + CVE(times) ----------------
__global__ void embed_kernel(const float* __restrict__ times, const float* __restrict__ values,
                             const int* __restrict__ varis, const float* __restrict__ emb,
                             const float* __restrict__ vW1, const float* __restrict__ vb1,
                             const float* __restrict__ vW2, const float* __restrict__ tW1,
                             const float* __restrict__ tb1, const float* __restrict__ tW2,
                             float* __restrict__ X, float* __restrict__ maskf)
{
    __shared__ float sv[4][8], st[4][8];
    int r = threadIdx.x >> 6, c = threadIdx.x & 63;
    int row = blockIdx.x * 4 + r;
    float vval = values[row];
    float tval = times[row];
    if (c < 8)       sv[r][c]   = tanhf(vval * vW1[c]   + vb1[c]);
    else if (c < 16) st[r][c-8] = tanhf(tval * tW1[c-8] + tb1[c-8]);
    __syncthreads();
    int vi = varis[row];
    float x = emb[vi*64 + c];
    #pragma unroll
    for (int u = 0; u < 8; u++) {
        x += sv[r][u] * vW2[u*64 + c];
        x += st[r][u] * tW2[u*64 + c];
    }
    X[row*64 + c] = x;
    if (c == 0) maskf[row] = (vi > 0) ? 1.0f : 0.0f;
}

// ---------------- demo encoder: tanh(tanh(demo@dW1)@dW2) ----------------
__global__ void demo_kernel(const float* __restrict__ demo, const float* __restrict__ dW1,
                            const float* __restrict__ db1, const float* __restrict__ dW2,
                            const float* __restrict__ db2, float* __restrict__ de)
{
    __shared__ float hh[128];
    int b = blockIdx.x, j = threadIdx.x;
    float a = db1[j];
    for (int i = 0; i < 50; i++) a += demo[b*50 + i] * dW1[i*128 + j];
    hh[j] = tanhf(a);
    __syncthreads();
    if (j < 64) {
        float e = db2[j];
        #pragma unroll
        for (int u = 0; u < 128; u++) e += hh[u] * dW2[u*64 + j];
        de[b*64 + j] = tanhf(e);
    }
}

// ---------------- fused QKV projection ----------------
__global__ void qkv_kernel(const float* __restrict__ X,
                           const float* __restrict__ Wq, const float* __restrict__ Wk,
                           const float* __restrict__ Wv,
                           float* __restrict__ Q, float* __restrict__ K, float* __restrict__ V)
{
    extern __shared__ float sm[];
    float* sW = sm;            // 12288 floats
    float* sX = sm + 12288;    // 1024 floats (16 rows x 64)
    const int tid = threadIdx.x;
    for (int idx = tid; idx < 12288; idx += 192) {
        int dd = idx / 192, col = idx % 192;
        int mat = col >> 6, c = col & 63;
        const float* W = (mat == 0) ? Wq : ((mat == 1) ? Wk : Wv);
        sW[idx] = W[((c >> 3) << 9) + (dd << 3) + (c & 7)];   // W[h][dd][k]
    }
    int rowbase = blockIdx.x * 16;
    for (int idx = tid; idx < 16*64; idx += 192) sX[idx] = X[rowbase*64 + idx];
    __syncthreads();

    int col4 = tid % 48;            // group of 4 contiguous cols
    int rr   = tid / 48;            // 0..3
    const float4* sW4 = (const float4*)sW;
    int col = col4 * 4;
    int mat = col >> 6, c = col & 63;
    float* OUT = (mat == 0) ? Q : ((mat == 1) ? K : V);
    int h = c >> 3, k = c & 7;
    for (int it = 0; it < 4; it++) {
        int rl = it*4 + rr;
        const float* xr = sX + rl*64;
        float4 acc = make_float4(0.f, 0.f, 0.f, 0.f);
        #pragma unroll
        for (int dd = 0; dd < 64; dd++) {
            float4 w = sW4[dd*48 + col4];
            float  x = xr[dd];
            acc.x += x*w.x; acc.y += x*w.y; acc.z += x*w.z; acc.w += x*w.w;
        }
        int row = rowbase + rl;
        int b = row >> 10, l = row & 1023;
        *((float4*)(OUT + ((((b<<3) + h) << 10) + l)*8 + k)) = acc;
    }
}

// ---------------- attention v3: packed f32x2 FMA ----------------
// Mask folded into K; no online max (shift-invariance); q pre-scaled by log2e
// so p = ex2(s). 2 queries/thread; dot+accum run on FFMA2 (2 FMA/lane/slot).
__global__ void __launch_bounds__(256, 3)
attn_kernel(const float* __restrict__ Q, const float* __restrict__ K,
            const float* __restrict__ V, const float* __restrict__ maskf,
            float* __restrict__ C)
{
    extern __shared__ float sm[];
    float* sK = sm;          // 8192
    float* sV = sm + 8192;   // 8192
    int bh = blockIdx.x >> 1;
    int qh = blockIdx.x & 1;
    int b = bh >> 3, h = bh & 7;
    const float* Kp = K + bh * 8192;
    const float* Vp = V + bh * 8192;
    const float* mp = maskf + b * 1024;
    int tid = threadIdx.x;  // 256
    for (int i = tid; i < 8192; i += 256) {
        sV[i] = Vp[i];
        sK[i] = Kp[i] * mp[i >> 3];   // zero masked K rows -> score 0 -> ex2(0)=1
    }
    __syncthreads();

    int l0 = qh*512 + tid;
    int l1 = l0 + 256;
    const float* qp0 = Q + (bh*1024 + l0)*8;
    const float* qp1 = Q + (bh*1024 + l1)*8;
    const float LOG2E = 1.4426950408889634f;
    unsigned long long q0p[4], q1p[4];
    #pragma unroll
    for (int j = 0; j < 4; j++) {
        q0p[j] = pk2(qp0[2*j] * LOG2E, qp0[2*j+1] * LOG2E);
        q1p[j] = pk2(qp1[2*j] * LOG2E, qp1[2*j+1] * LOG2E);
    }

    float ssum0 = 0.f, ssum1 = 0.f;
    unsigned long long acc0[4] = {0ull,0ull,0ull,0ull};
    unsigned long long acc1[4] = {0ull,0ull,0ull,0ull};
    const double2* sK2 = (const double2*)sK;   // 2 double2 per 32B row
    const double2* sV2 = (const double2*)sV;
    #pragma unroll 2
    for (int m = 0; m < 1024; m++) {
        double2 ka = sK2[m*2], kb = sK2[m*2 + 1];
        unsigned long long k0 = __double_as_longlong(ka.x);
        unsigned long long k1 = __double_as_longlong(ka.y);
        unsigned long long k2 = __double_as_longlong(kb.x);
        unsigned long long k3 = __double_as_longlong(kb.y);
        unsigned long long t0 = fma2(q0p[0], k0,
                              fma2(q0p[1], k1,
                              fma2(q0p[2], k2,
                              fma2(q0p[3], k3, 0ull))));
        unsigned long long t1 = fma2(q1p[0], k0,
                              fma2(q1p[1], k1,
                              fma2(q1p[2], k2,
                              fma2(q1p[3], k3, 0ull))));
        float a0, b0, a1, b1;
        upk2(t0, a0, b0);
        upk2(t1, a1, b1);
        float p0 = ex2f(a0 + b0);
        float p1 = ex2f(a1 + b1);
        ssum0 += p0; ssum1 += p1;
        unsigned long long p0p = pk2(p0, p0);
        unsigned long long p1p = pk2(p1, p1);
        double2 va = sV2[m*2], vb = sV2[m*2 + 1];
        unsigned long long v0 = __double_as_longlong(va.x);
        unsigned long long v1 = __double_as_longlong(va.y);
        unsigned long long v2 = __double_as_longlong(vb.x);
        unsigned long long v3 = __double_as_longlong(vb.y);
        acc0[0] = fma2(p0p, v0, acc0[0]);
        acc0[1] = fma2(p0p, v1, acc0[1]);
        acc0[2] = fma2(p0p, v2, acc0[2]);
        acc0[3] = fma2(p0p, v3, acc0[3]);
        acc1[0] = fma2(p1p, v0, acc1[0]);
        acc1[1] = fma2(p1p, v1, acc1[1]);
        acc1[2] = fma2(p1p, v2, acc1[2]);
        acc1[3] = fma2(p1p, v3, acc1[3]);
    }
    float inv0 = 1.f / ssum0;
    float inv1 = 1.f / ssum1;
    float o0[8], o1[8];
    #pragma unroll
    for (int j = 0; j < 4; j++) {
        upk2(acc0[j], o0[2*j], o0[2*j+1]);
        upk2(acc1[j], o1[2*j], o1[2*j+1]);
    }
    float* cp0 = C + (b*1024 + l0)*64 + h*8;
    float* cp1 = C + (b*1024 + l1)*64 + h*8;
    ((float4*)cp0)[0] = make_float4(o0[0]*inv0, o0[1]*inv0, o0[2]*inv0, o0[3]*inv0);
    ((float4*)cp0)[1] = make_float4(o0[4]*inv0, o0[5]*inv0, o0[6]*inv0, o0[7]*inv0);
    ((float4*)cp1)[0] = make_float4(o1[0]*inv1, o1[1]*inv1, o1[2]*inv1, o1[3]*inv1);
    ((float4*)cp1)[1] = make_float4(o1[4]*inv1, o1[5]*inv1, o1[6]*inv1, o1[7]*inv1);
}

// ---------------- out-projection + residual + LayerNorm (warp-per-row) ----------------
__global__ void proj_ln_kernel(float* __restrict__ X, const float* __restrict__ C,
                               const float* __restrict__ Wo,
                               const float* __restrict__ gamma, const float* __restrict__ beta)
{
    __shared__ float sWo[4096];
    __shared__ float sC[512];
    int tid = threadIdx.x;  // 256 = 8 warps = 8 rows
    for (int i = tid; i < 4096; i += 256) sWo[i] = Wo[i];  // [dd][c]
    int rowbase = blockIdx.x * 8;
    for (int i = tid; i < 512; i += 256) sC[i] = C[rowbase*64 + i];
    __syncthreads();

    int w = tid >> 5, lane = tid & 31;
    int row = rowbase + w;
    int c0 = lane, c1 = lane + 32;
    float y0 = X[row*64 + c0];
    float y1 = X[row*64 + c1];
    const float* cr = sC + w*64;
    #pragma unroll
    for (int dd = 0; dd < 64; dd++) {
        float cv = cr[dd];
        y0 += cv * sWo[dd*64 + c0];
        y1 += cv * sWo[dd*64 + c1];
    }
    float s  = y0 + y1;
    float s2 = y0*y0 + y1*y1;
    #pragma unroll
    for (int o = 16; o > 0; o >>= 1) {
        s  += __shfl_xor_sync(0xffffffffu, s,  o);
        s2 += __shfl_xor_sync(0xffffffffu, s2, o);
    }
    float mean = s * (1.f/64.f);
    float rstd = rsqrtf(s2*(1.f/64.f) - mean*mean + 1e-14f);
    float g = gamma[0], bt = beta[0];
    X[row*64 + c0] = (y0 - mean) * rstd * g + bt;
    X[row*64 + c1] = (y1 - mean) * rstd * g + bt;
}

// ---------------- FFN + residual + LayerNorm ----------------
__global__ void ffn_kernel(float* __restrict__ X,
                           const float* __restrict__ W1, const float* __restrict__ b1,
                           const float* __restrict__ W2, const float* __restrict__ b2,
                           const float* __restrict__ gamma, const float* __restrict__ beta)
{
    extern __shared__ float sm[];
    float* sW1   = sm;            // 8192  [dd][128]
    float* sW2   = sm + 8192;     // 8192  [j][64]
    float* sX    = sm + 16384;    // 512
    float* sH    = sm + 16896;    // 1024
    float* red   = sm + 17920;    // 512
    float* sstat = sm + 18432;    // 16
    int tid = threadIdx.x;  // 256
    for (int i = tid; i < 8192; i += 256) { sW1[i] = W1[i]; sW2[i] = W2[i]; }
    int rowbase = blockIdx.x * 8;
    for (int i = tid; i < 512; i += 256) sX[i] = X[rowbase*64 + i];
    __syncthreads();

    // stage 1: hidden = relu(X@W1 + b1)
    {
        int r = tid >> 5, jg = tid & 31;
        const float4* w4p = (const float4*)sW1;
        const float* xr = sX + r*64;
        float4 a = make_float4(b1[jg*4], b1[jg*4+1], b1[jg*4+2], b1[jg*4+3]);
        #pragma unroll
        for (int dd = 0; dd < 64; dd++) {
            float4 w = w4p[dd*32 + jg];
            float  x = xr[dd];
            a.x += x*w.x; a.y += x*w.y; a.z += x*w.z; a.w += x*w.w;
        }
        ((float4*)(sH + r*128))[jg] =
            make_float4(fmaxf(a.x,0.f), fmaxf(a.y,0.f), fmaxf(a.z,0.f), fmaxf(a.w,0.f));
    }
    __syncthreads();

    // stage 2: y = X + hidden@W2 + b2  (all 256 threads: 2 cols each)
    {
        int r = tid >> 5, cg = tid & 31;
        const float2* w2p = (const float2*)sW2;
        const float* hr = sH + r*128;
        int row = rowbase + r;
        float2 a  = *((const float2*)(X + row*64 + cg*2));
        float2 bb = *((const float2*)(b2 + cg*2));
        a.x += bb.x; a.y += bb.y;
        #pragma unroll
        for (int j = 0; j < 128; j++) {
            float2 w = w2p[j*32 + cg];
            float hv = hr[j];
            a.x += hv*w.x; a.y += hv*w.y;
        }
        ((float2*)(red + r*64))[cg] = a;
    }
    __syncthreads();
    if (tid < 8) {
        float s = 0.f, s2 = 0.f;
        const float* rr = red + tid*64;
        #pragma unroll
        for (int i = 0; i < 64; i++) { float v = rr[i]; s += v; s2 += v*v; }
        float mean = s * (1.f/64.f);
        sstat[tid*2]   = mean;
        sstat[tid*2+1] = rsqrtf(s2*(1.f/64.f) - mean*mean + 1e-14f);
    }
    __syncthreads();
    float g = gamma[0], bv = beta[0];
    #pragma unroll
    for (int p = 0; p < 2; p++) {
        int idx = tid + p*256;
        int r = idx >> 6;
        X[(rowbase + r)*64 + (idx & 63)] = (red[idx] - sstat[r*2]) * sstat[r*2+1] * g + bv;
    }
}

// ---------------- attention-pool logits: 8 rows/block, aW1 in smem ----------------
__global__ void aw_kernel(const float* __restrict__ X, const float* __restrict__ aW1,
                          const float* __restrict__ ab1, const float* __restrict__ aW2,
                          float* __restrict__ awl)
{
    __shared__ float sW[8192];     // aW1 [64][128]
    __shared__ float sB[128];      // ab1
    __shared__ float sA2[128];     // aW2
    __shared__ float sXr[512];     // 8 rows x 64
    int tid = threadIdx.x;  // 256
    for (int i = tid; i < 8192; i += 256) sW[i] = aW1[i];
    if (tid < 128) { sB[tid] = ab1[tid]; sA2[tid] = aW2[tid]; }
    int rowbase = blockIdx.x * 8;
    for (int i = tid; i < 512; i += 256) sXr[i] = X[rowbase*64 + i];
    __syncthreads();

    int w = tid >> 5, lane = tid & 31;
    const float* xr = sXr + w*64;
    int j4 = lane * 4;
    float4 a = make_float4(sB[j4], sB[j4+1], sB[j4+2], sB[j4+3]);
    const float4* w4p = (const float4*)sW;
    #pragma unroll
    for (int dd = 0; dd < 64; dd++) {
        float4 wv = w4p[dd*32 + lane];
        float  x  = xr[dd];
        a.x += x*wv.x; a.y += x*wv.y; a.z += x*wv.z; a.w += x*wv.w;
    }
    float val = tanhf(a.x)*sA2[j4] + tanhf(a.y)*sA2[j4+1]
              + tanhf(a.z)*sA2[j4+2] + tanhf(a.w)*sA2[j4+3];
    #pragma unroll
    for (int o = 16; o > 0; o >>= 1) val += __shfl_xor_sync(0xffffffffu, val, o);
    if (lane == 0) awl[rowbase + w] = val;
}

// ---------------- masked softmax pool + head ----------------
__global__ void pool_kernel(const float* __restrict__ X, const float* __restrict__ awl,
                            const float* __restrict__ maskf, const float* __restrict__ demoe,
                            const float* __restrict__ Wout, const float* __restrict__ bout,
                            float* __restrict__ out)
{
    __shared__ float sw[1024];
    __shared__ float red[256];
    __shared__ float part[4][64];
    __shared__ float conc[128];
    int b = blockIdx.x, tid = threadIdx.x;  // 256
    for (int l = tid; l < 1024; l += 256)
        sw[l] = (maskf[b*1024 + l] != 0.f) ? awl[b*1024 + l] : -1e30f;
    __syncthreads();
    float mx = -3.0e38f;
    for (int l = tid; l < 1024; l += 256) mx = fmaxf(mx, sw[l]);
    red[tid] = mx; __syncthreads();
    for (int st = 128; st > 0; st >>= 1) {
        if (tid < st) red[tid] = fmaxf(red[tid], red[tid + st]);
        __syncthreads();
    }
    mx = red[0];
    __syncthreads();
    float se = 0.f;
    for (int l = tid; l < 1024; l += 256) { float e = __expf(sw[l] - mx); sw[l] = e; se += e; }
    red[tid] = se; __syncthreads();
    for (int st = 128; st > 0; st >>= 1) {
        if (tid < st) red[tid] += red[tid + st];
        __syncthreads();
    }
    float inv = 1.f / red[0];
    __syncthreads();
    // fused = sum_l sw[l]*X[l,:] — all 256 threads (64 cols x 4 chunks)
    {
        int col = tid & 63, ch = tid >> 6;
        const float* xb = X + b*1024*64;
        float f = 0.f;
        for (int i = 0; i < 256; i++) {
            int l = ch*256 + i;
            f += sw[l] * xb[l*64 + col];
        }
        part[ch][col] = f;
    }
    __syncthreads();
    if (tid < 64) {
        conc[tid] = (part[0][tid] + part[1][tid] + part[2][tid] + part[3][tid]) * inv;
    } else if (tid < 128) {
        conc[tid] = demoe[b*64 + (tid - 64)];
    }
    __syncthreads();
    if (tid < 128) red[tid] = conc[tid] * Wout[tid]; else red[tid] = 0.f;
    __syncthreads();
    for (int st = 128; st > 0; st >>= 1) {
        if (tid < st) red[tid] += red[tid + st];
        __syncthreads();
    }
    if (tid == 0) out[b] = 1.f / (1.f + __expf(-(red[0] + bout[0])));
}

// ---------------- launcher ----------------
extern "C" void kernel_launch(void* const* d_in, const int* in_sizes, int n_in,
                              void* d_out, int out_size)
{
    const float* demo  = (const float*)d_in[0];
    const float* times = (const float*)d_in[1];
    const float* values= (const float*)d_in[2];
    const int*   varis = (const int*)  d_in[3];
    const float* emb   = (const float*)d_in[4];
    const float* vW1   = (const float*)d_in[5];
    const float* vb1   = (const float*)d_in[6];
    const float* vW2   = (const float*)d_in[7];
    const float* tW1   = (const float*)d_in[8];
    const float* tb1   = (const float*)d_in[9];
    const float* tW2   = (const float*)d_in[10];
    const float* Wq    = (const float*)d_in[11];
    const float* Wk    = (const float*)d_in[12];
    const float* Wv    = (const float*)d_in[13];
    const float* Wo    = (const float*)d_in[14];
    const float* W1    = (const float*)d_in[15];
    const float* b1    = (const float*)d_in[16];
    const float* W2    = (const float*)d_in[17];
    const float* b2    = (const float*)d_in[18];
    const float* gamma = (const float*)d_in[19];
    const float* beta  = (const float*)d_in[20];
    const float* aW1   = (const float*)d_in[21];
    const float* ab1   = (const float*)d_in[22];
    const float* aW2   = (const float*)d_in[23];
    const float* dW1   = (const float*)d_in[24];
    const float* db1   = (const float*)d_in[25];
    const float* dW2   = (const float*)d_in[26];
    const float* db2   = (const float*)d_in[27];
    const float* Wout  = (const float*)d_in[28];
    const float* bout  = (const float*)d_in[29];
    float* out = (float*)d_out;

    float *X, *Qb, *Kb, *Vb, *Cb, *de, *mk, *awl;
    cudaGetSymbolAddress((void**)&X,   g_X);
    cudaGetSymbolAddress((void**)&Qb,  g_Q);
    cudaGetSymbolAddress((void**)&Kb,  g_K);
    cudaGetSymbolAddress((void**)&Vb,  g_V);
    cudaGetSymbolAddress((void**)&Cb,  g_C);
    cudaGetSymbolAddress((void**)&de,  g_demo);
    cudaGetSymbolAddress((void**)&mk,  g_mask);
    cudaGetSymbolAddress((void**)&awl, g_awl);

    cudaFuncSetAttribute(qkv_kernel,  cudaFuncAttributeMaxDynamicSharedMemorySize, 53248);
    cudaFuncSetAttribute(attn_kernel, cudaFuncAttributeMaxDynamicSharedMemorySize, 65536);
    cudaFuncSetAttribute(ffn_kernel,  cudaFuncAttributeMaxDynamicSharedMemorySize, 73792);

    embed_kernel<<<4096, 256>>>(times, values, varis, emb, vW1, vb1, vW2, tW1, tb1, tW2, X, mk);
    demo_kernel<<<16, 128>>>(demo, dW1, db1, dW2, db2, de);

    for (int i = 0; i < 2; i++) {
        qkv_kernel<<<1024, 192, 53248>>>(X, Wq + i*4096, Wk + i*4096, Wv + i*4096, Qb, Kb, Vb);
        attn_kernel<<<256, 256, 65536>>>(Qb, Kb, Vb, mk, Cb);
        proj_ln_kernel<<<2048, 256>>>(X, Cb, Wo + i*4096, gamma + 2*i, beta + 2*i);
        ffn_kernel<<<2048, 256, 73792>>>(X, W1 + i*8192, b1 + i*128, W2 + i*8192, b2 + i*64,
                                         gamma + 2*i + 1, beta + 2*i + 1);
    }

    aw_kernel<<<2048, 256>>>(X, aW1, ab1, aW2, awl);
    pool_kernel<<<16, 256>>>(X, awl, mk, de, Wout, bout, out);
}